// round 11
// baseline (speedup 1.0000x reference)
#include <cuda_runtime.h>

// Problem constants
#define Bc 4
#define Lc 2048
#define Dc 8192
#define Kc 4
#define QKc 2048
#define Vc 4096

#define CHUNK 64
#define THREADS 256
#define UNROLL 8
#define NGROUPS (CHUNK / UNROLL)
#define D4 (Dc / 4)            // 2048 float4 lanes across D

// output layout: [ q (B,L,QK) | k (B,L,QK) | v (B,L,V) | new_cache (B,D,K) ]
// all offsets fit comfortably in int32 (total out = 67,141,632 floats)
#define Q_F4   (Bc * Lc * (QKc / 4))            // 4,194,304 float4
#define V_F4   (Bc * Lc * (Vc / 4))             // 8,388,608 float4
#define NC_OFF4 (2 * Q_F4 + V_F4)               // float4 offset of new_cache

__device__ __forceinline__ float silu(float v) {
    // fast sigmoid: MUFU.EX2 + MUFU.RCP path (~2 ulp, tolerance is 1e-3)
    const float e = __expf(-v);
    return v * __fdividef(1.0f, 1.0f + e);
}

// min-blocks=2 caps regs at 128: keeps 2 blocks/SM (16 warps) while leaving room
// for the double buffer. R9 taught us not to squeeze below what the buffers need.
__global__ __launch_bounds__(THREADS, 2)
void conv_silu_kernel(const float* __restrict__ x,
                      const float* __restrict__ cache,
                      const float* __restrict__ weight,
                      float* __restrict__ out)
{
    const int d4 = blockIdx.x * THREADS + threadIdx.x;   // float4 lane in D: 0..2047
    const int d  = d4 * 4;                               // first scalar channel
    const int b  = blockIdx.z;
    const int l0 = blockIdx.y * CHUNK;
    const bool last = (l0 + CHUNK == Lc);

    const float4* x4 = (const float4*)x;
    const float4* w4 = (const float4*)weight;            // weight (D,K=4): row d = one float4

    // per-channel weights for d..d+3
    const float4 w0 = w4[d + 0];
    const float4 w1 = w4[d + 1];
    const float4 w2 = w4[d + 2];
    const float4 w3 = w4[d + 3];

    // sliding window: r0..r2 = xf rows l0..l0+2 (i.e., x rows l0-3..l0-1)
    float4 r0, r1, r2;
    if (l0 == 0) {
        // xf[0..2] come from cache[:, :, 1..3]; cache (B,D,K=4) -> float4 per channel
        const float4* c4 = (const float4*)cache + b * Dc + d;
        const float4 c0 = c4[0], c1 = c4[1], c2 = c4[2], c3 = c4[3];
        r0 = make_float4(c0.y, c1.y, c2.y, c3.y);
        r1 = make_float4(c0.z, c1.z, c2.z, c3.z);
        r2 = make_float4(c0.w, c1.w, c2.w, c3.w);
    } else {
        const float4* xb = x4 + (b * Lc + (l0 - 3)) * D4 + d4;
        r0 = __ldcs(&xb[0]);
        r1 = __ldcs(&xb[D4]);
        r2 = __ldcs(&xb[2 * D4]);
    }

    // output base: segment boundaries (2048, 4096) are float4-aligned, so the whole
    // float4 lane lives in one segment. 32-bit offsets throughout.
    int obase, stride4;
    if (d < QKc) {                                // q
        stride4 = QKc / 4;
        obase   = (b * Lc + l0) * stride4 + d4;
    } else if (d < 2 * QKc) {                     // k
        stride4 = QKc / 4;
        obase   = Q_F4 + (b * Lc + l0) * stride4 + (d4 - QKc / 4);
    } else {                                      // v
        stride4 = Vc / 4;
        obase   = 2 * Q_F4 + (b * Lc + l0) * stride4 + (d4 - 2 * (QKc / 4));
    }
    float4*       optr = (float4*)out + obase;
    const float4* xin  = x4 + (b * Lc + l0) * D4 + d4;   // xf[l+3] == x[b, l, :]

    // ---- software pipeline: double-buffered register prefetch ----
    // invariant: while computing group g, the 8 loads of group g+1 are in flight,
    // so each warp keeps ~8 LDG.128 outstanding at ALL times (no drain window).
    float4 bufA[UNROLL], bufB[UNROLL];

#pragma unroll
    for (int u = 0; u < UNROLL; ++u)                     // prologue: group 0
        bufA[u] = __ldcs(&xin[u * D4]);
    xin += UNROLL * D4;

#pragma unroll 1
    for (int g = 0; g < NGROUPS; ++g) {
        const bool even = !(g & 1);
        float4* cur = even ? bufA : bufB;
        float4* nxt = even ? bufB : bufA;

        if (g + 1 < NGROUPS) {
#pragma unroll
            for (int u = 0; u < UNROLL; ++u)             // prefetch group g+1
                nxt[u] = __ldcs(&xin[u * D4]);
            xin += UNROLL * D4;
        }

#pragma unroll
        for (int u = 0; u < UNROLL; ++u) {
            const float4 r3 = cur[u];
            float4 y;
            y.x = silu(w0.x * r0.x + w0.y * r1.x + w0.z * r2.x + w0.w * r3.x);
            y.y = silu(w1.x * r0.y + w1.y * r1.y + w1.z * r2.y + w1.w * r3.y);
            y.z = silu(w2.x * r0.z + w2.y * r1.z + w2.z * r2.z + w2.w * r3.z);
            y.w = silu(w3.x * r0.w + w3.y * r1.w + w3.z * r2.w + w3.w * r3.w);
            __stcs(&optr[u * stride4], y);

            // fused conv-state update: in the very last iteration the window regs
            // hold exactly x rows L-4..L-1 for channels d..d+3.
            // new_cache (B,D,K): 4x4 register transpose, 4 coalesced float4 stores.
            if (u == UNROLL - 1 && g == NGROUPS - 1 && last) {
                float4* nc = (float4*)out + NC_OFF4 + b * Dc + d;
                nc[0] = make_float4(r0.x, r1.x, r2.x, r3.x);
                nc[1] = make_float4(r0.y, r1.y, r2.y, r3.y);
                nc[2] = make_float4(r0.z, r1.z, r2.z, r3.z);
                nc[3] = make_float4(r0.w, r1.w, r2.w, r3.w);
            }

            r0 = r1; r1 = r2; r2 = r3;
        }
        optr += UNROLL * stride4;
    }
}

extern "C" void kernel_launch(void* const* d_in, const int* in_sizes, int n_in,
                              void* d_out, int out_size)
{
    const float* x      = (const float*)d_in[0];
    const float* cache  = (const float*)d_in[1];
    const float* weight = (const float*)d_in[2];
    float*       out    = (float*)d_out;

    dim3 grid(D4 / THREADS, Lc / CHUNK, Bc);   // (8, 32, 4) = 1024 blocks
    conv_silu_kernel<<<grid, THREADS>>>(x, cache, weight, out);
}

// round 12
// speedup vs baseline: 1.2958x; 1.2958x over previous
#include <cuda_runtime.h>
#include <cstdint>

// Problem constants
#define Bc 4
#define Lc 2048
#define Dc 8192
#define Kc 4
#define QKc 2048
#define Vc 4096

#define CHUNK 64
#define THREADS 256
#define UNROLL 8
#define NGROUPS (CHUNK / UNROLL)           // 8
#define D4 (Dc / 4)                        // 2048 float4 lanes across D

#define STAGE_F4   (THREADS * UNROLL)      // 2048 float4 per stage
#define SMEM_BYTES (2 * STAGE_F4 * 16)     // 65536

// output layout: [ q (B,L,QK) | k (B,L,QK) | v (B,L,V) | new_cache (B,D,K) ]
#define Q_F4    (Bc * Lc * (QKc / 4))      // 4,194,304 float4
#define V_F4    (Bc * Lc * (Vc / 4))       // 8,388,608 float4
#define NC_OFF4 (2 * Q_F4 + V_F4)          // float4 offset of new_cache

__device__ __forceinline__ float silu(float v) {
    const float e = __expf(-v);
    return v * __fdividef(1.0f, 1.0f + e);
}

__device__ __forceinline__ uint32_t smem_u32(const void* p) {
    return (uint32_t)__cvta_generic_to_shared(p);
}
__device__ __forceinline__ void cp16(uint32_t smem_addr, const float4* gptr) {
    asm volatile("cp.async.cg.shared.global [%0], [%1], 16;\n"
                 :: "r"(smem_addr), "l"(gptr) : "memory");
}
#define CP_COMMIT()  asm volatile("cp.async.commit_group;\n" ::: "memory")
#define CP_WAIT(N)   asm volatile("cp.async.wait_group %0;\n" :: "n"(N) : "memory")

__global__ __launch_bounds__(THREADS)
void conv_silu_kernel(const float* __restrict__ x,
                      const float* __restrict__ cache,
                      const float* __restrict__ weight,
                      float* __restrict__ out)
{
    extern __shared__ float4 smem[];       // [2][UNROLL][THREADS]

    const int tid = threadIdx.x;
    const int d4  = blockIdx.x * THREADS + tid;          // float4 lane in D: 0..2047
    const int d   = d4 * 4;                              // first scalar channel
    const int b   = blockIdx.z;
    const int l0  = blockIdx.y * CHUNK;
    const bool last = (l0 + CHUNK == Lc);

    const float4* x4 = (const float4*)x;
    const float4* w4 = (const float4*)weight;            // weight (D,K=4): row d = one float4

    const float4 w0 = w4[d + 0];
    const float4 w1 = w4[d + 1];
    const float4 w2 = w4[d + 2];
    const float4 w3 = w4[d + 3];

    // sliding window: r0..r2 = xf rows l0..l0+2 (x rows l0-3..l0-1)
    float4 r0, r1, r2;
    if (l0 == 0) {
        const float4* c4 = (const float4*)cache + b * Dc + d;
        const float4 c0 = c4[0], c1 = c4[1], c2 = c4[2], c3 = c4[3];
        r0 = make_float4(c0.y, c1.y, c2.y, c3.y);
        r1 = make_float4(c0.z, c1.z, c2.z, c3.z);
        r2 = make_float4(c0.w, c1.w, c2.w, c3.w);
    } else {
        const float4* xb = x4 + (b * Lc + (l0 - 3)) * D4 + d4;
        r0 = __ldcs(&xb[0]);
        r1 = __ldcs(&xb[D4]);
        r2 = __ldcs(&xb[2 * D4]);
    }

    // output base: q/k/v split boundaries are float4-aligned per lane
    int obase, stride4;
    if (d < QKc) {                                // q
        stride4 = QKc / 4;
        obase   = (b * Lc + l0) * stride4 + d4;
    } else if (d < 2 * QKc) {                     // k
        stride4 = QKc / 4;
        obase   = Q_F4 + (b * Lc + l0) * stride4 + (d4 - QKc / 4);
    } else {                                      // v
        stride4 = Vc / 4;
        obase   = 2 * Q_F4 + (b * Lc + l0) * stride4 + (d4 - 2 * (QKc / 4));
    }
    float4*       optr = (float4*)out + obase;
    const float4* xin  = x4 + (b * Lc + l0) * D4 + d4;   // row l0 onward

    // smem addressing: stage s, row u, this thread -> smem[s*2048 + u*256 + tid]
    const uint32_t my_smem = smem_u32(smem) + (uint32_t)tid * 16u;
    const float4*  my_rd   = smem + tid;

    // ---- async pipeline: each thread only ever consumes its OWN cp.async data,
    // so no __syncthreads is needed; cp.async.wait_group gives per-thread ordering.

    // prologue: prefetch group 0 into stage 0
#pragma unroll
    for (int u = 0; u < UNROLL; ++u)
        cp16(my_smem + (uint32_t)(u * THREADS) * 16u, &xin[u * D4]);
    CP_COMMIT();
    xin += UNROLL * D4;

#pragma unroll 1
    for (int g = 0; g < NGROUPS - 1; ++g) {
        const int cs = g & 1;                    // compute stage
        const int ps = cs ^ 1;                   // prefetch stage

        // prefetch group g+1 (stays in flight through this group's compute)
        const uint32_t pbase = my_smem + (uint32_t)(ps * STAGE_F4) * 16u;
#pragma unroll
        for (int u = 0; u < UNROLL; ++u)
            cp16(pbase + (uint32_t)(u * THREADS) * 16u, &xin[u * D4]);
        CP_COMMIT();
        xin += UNROLL * D4;

        CP_WAIT(1);                              // group g landed; g+1 still flying

        const float4* rd = my_rd + cs * STAGE_F4;
#pragma unroll
        for (int u = 0; u < UNROLL; ++u) {
            const float4 r3 = rd[u * THREADS];
            float4 y;
            y.x = silu(w0.x * r0.x + w0.y * r1.x + w0.z * r2.x + w0.w * r3.x);
            y.y = silu(w1.x * r0.y + w1.y * r1.y + w1.z * r2.y + w1.w * r3.y);
            y.z = silu(w2.x * r0.z + w2.y * r1.z + w2.z * r2.z + w2.w * r3.z);
            y.w = silu(w3.x * r0.w + w3.y * r1.w + w3.z * r2.w + w3.w * r3.w);
            __stcs(&optr[u * stride4], y);
            r0 = r1; r1 = r2; r2 = r3;
        }
        optr += UNROLL * stride4;
    }

    // epilogue: last group (stage (NGROUPS-1)&1 = 1)
    CP_WAIT(0);
    {
        const float4* rd = my_rd + ((NGROUPS - 1) & 1) * STAGE_F4;
#pragma unroll
        for (int u = 0; u < UNROLL; ++u) {
            const float4 r3 = rd[u * THREADS];
            float4 y;
            y.x = silu(w0.x * r0.x + w0.y * r1.x + w0.z * r2.x + w0.w * r3.x);
            y.y = silu(w1.x * r0.y + w1.y * r1.y + w1.z * r2.y + w1.w * r3.y);
            y.z = silu(w2.x * r0.z + w2.y * r1.z + w2.z * r2.z + w2.w * r3.z);
            y.w = silu(w3.x * r0.w + w3.y * r1.w + w3.z * r2.w + w3.w * r3.w);
            __stcs(&optr[u * stride4], y);

            // fused conv-state update: final iteration holds x rows L-4..L-1
            // for channels d..d+3 in (r0,r1,r2,r3). 4x4 register transpose.
            if (u == UNROLL - 1 && last) {
                float4* nc = (float4*)out + NC_OFF4 + b * Dc + d;
                nc[0] = make_float4(r0.x, r1.x, r2.x, r3.x);
                nc[1] = make_float4(r0.y, r1.y, r2.y, r3.y);
                nc[2] = make_float4(r0.z, r1.z, r2.z, r3.z);
                nc[3] = make_float4(r0.w, r1.w, r2.w, r3.w);
            }
            r0 = r1; r1 = r2; r2 = r3;
        }
    }
}

extern "C" void kernel_launch(void* const* d_in, const int* in_sizes, int n_in,
                              void* d_out, int out_size)
{
    const float* x      = (const float*)d_in[0];
    const float* cache  = (const float*)d_in[1];
    const float* weight = (const float*)d_in[2];
    float*       out    = (float*)d_out;

    // opt-in to 64KB dynamic smem (idempotent; executes immediately even under capture)
    cudaFuncSetAttribute(conv_silu_kernel,
                         cudaFuncAttributeMaxDynamicSharedMemorySize, SMEM_BYTES);

    dim3 grid(D4 / THREADS, Lc / CHUNK, Bc);   // (8, 32, 4) = 1024 blocks
    conv_silu_kernel<<<grid, THREADS, SMEM_BYTES>>>(x, cache, weight, out);
}